// round 12
// baseline (speedup 1.0000x reference)
#include <cuda_runtime.h>
#include <cuda_fp16.h>
#include <math.h>
#include <stdint.h>

// ---------------------------------------------------------------------------
// GCN_27797028339919 — round 12
//  * aggregate-then-multiply: layer-1 neighborhood aggregation done in
//    x-space (256-dim) for ONLY the ~30k nodes S = roots ∪ in-neigh(roots);
//    then a compact [Scnt,256]@[256,128] GEMM. The two full 100k-row GEMMs
//    are gone (3.3x fewer tensor FLOPs).
//  * compact also builds inv[node] -> compact index for layer-2 gather.
//  * layer 2 at roots only (linearity); fused head. Multi-stream pipeline.
// ---------------------------------------------------------------------------

#define MAX_N 100000
#define MAX_R 2048
#define SLOTS 64

__device__ uint32_t g_xh[(size_t)MAX_N * 128];      // x as half2 (256 halves/row)
__device__ uint32_t g_gx_td[(size_t)MAX_N * 128];   // aggregated z (compact, fp16)
__device__ uint32_t g_gx_bu[(size_t)MAX_N * 128];
__device__ uint32_t g_B_td[(size_t)MAX_N * 64];     // B1s (compact, fp16)
__device__ uint32_t g_B_bu[(size_t)MAX_N * 64];
__device__ uint32_t g_wh[(size_t)384 * 128];        // packed weights
__device__ int   g_cur_td[MAX_N];
__device__ int   g_cur_bu[MAX_N];
__device__ float g_dinv_td[MAX_N];
__device__ float g_dinv_bu[MAX_N];
__device__ int   g_srcs_td[(size_t)MAX_N * SLOTS];
__device__ int   g_srcs_bu[(size_t)MAX_N * SLOTS];
__device__ char  g_mark_td[MAX_N];
__device__ char  g_mark_bu[MAX_N];
__device__ int   g_list_td[MAX_N];
__device__ int   g_list_bu[MAX_N];
__device__ int   g_inv_td[MAX_N];
__device__ int   g_inv_bu[MAX_N];
__device__ int   g_listcnt[2];
__device__ uint32_t g_g_td[(size_t)MAX_R * 64];
__device__ uint32_t g_g_bu[(size_t)MAX_R * 64];
__device__ uint32_t g_r_td[(size_t)MAX_R * 64];
__device__ uint32_t g_r_bu[(size_t)MAX_R * 64];

static inline int ceil_div(int a, int b) { return (a + b - 1) / b; }

__device__ __forceinline__ uint32_t h2_u32(__half2 h) {
    return *reinterpret_cast<uint32_t*>(&h);
}
__device__ __forceinline__ __half2 u32_h2(uint32_t u) {
    return *reinterpret_cast<__half2*>(&u);
}
__device__ __forceinline__ float4 h4_to_f4(uint2 v) {
    float2 lo = __half22float2(u32_h2(v.x));
    float2 hi = __half22float2(u32_h2(v.y));
    return make_float4(lo.x, lo.y, hi.x, hi.y);
}
__device__ __forceinline__ float elu1(float x) {
    return x > 0.f ? x : expm1f(x);
}

// ---------------- prep kernels ----------------

__global__ void convert_x_kernel(const float* __restrict__ x,
                                 uint32_t* __restrict__ xh, int n4) {
    int i = blockIdx.x * blockDim.x + threadIdx.x;
    if (i >= n4) return;
    float4 v = *(const float4*)&x[(size_t)i * 4];
    uint2 o;
    o.x = h2_u32(__floats2half2_rn(v.x, v.y));
    o.y = h2_u32(__floats2half2_rn(v.z, v.w));
    *(uint2*)&xh[(size_t)i * 2] = o;
}

// pack all weights pair-major: w1[0:128), w2[128:192), w3[192:320), w4[320:384)
__global__ void pack_w_kernel(const float* __restrict__ w1, const float* __restrict__ w2,
                              const float* __restrict__ w3, const float* __restrict__ w4,
                              uint32_t* __restrict__ wh) {
    int i = blockIdx.x * blockDim.x + threadIdx.x;
    if (i >= 384 * 128) return;
    int prow = i >> 7;
    int n = i & 127;
    const float* w; int p;
    if (prow < 128)      { w = w1; p = prow; }
    else if (prow < 192) { w = w2; p = prow - 128; }
    else if (prow < 320) { w = w3; p = prow - 192; }
    else                 { w = w4; p = prow - 320; }
    float a = w[(size_t)(2 * p) * 128 + n];
    float b = w[(size_t)(2 * p + 1) * 128 + n];
    wh[i] = h2_u32(__floats2half2_rn(a, b));
}

__global__ void zero_kernel(int* ua, int* ub, char* ma, char* mb, int* lc, int n) {
    int i = blockIdx.x * blockDim.x + threadIdx.x;
    if (i < n) { ua[i] = 0; ub[i] = 0; ma[i] = 0; mb[i] = 0; }
    if (i < 2) lc[i] = 0;
}

__global__ void fill_kernel(const int* __restrict__ src0, const int* __restrict__ dst0,
                            const int* __restrict__ src1, const int* __restrict__ dst1,
                            int* cur0, int* cur1,
                            int* __restrict__ srcs0, int* __restrict__ srcs1, int E) {
    int e = blockIdx.x * blockDim.x + threadIdx.x;
    if (e >= E) return;
    const int* src; const int* dst; int* cur; int* srcs;
    if (blockIdx.y) { src = src1; dst = dst1; cur = cur1; srcs = srcs1; }
    else            { src = src0; dst = dst0; cur = cur0; srcs = srcs0; }
    int d = __ldg(&dst[e]);
    int p = atomicAdd(&cur[d], 1);
    if (p < SLOTS) srcs[(size_t)d * SLOTS + p] = __ldg(&src[e]);
}

__global__ void dinv_kernel(const int* ca, const int* cb, float* da, float* db, int n) {
    int i = blockIdx.x * blockDim.x + threadIdx.x;
    if (i < n) {
        da[i] = rsqrtf((float)ca[i] + 1.0f);
        db[i] = rsqrtf((float)cb[i] + 1.0f);
    }
}

__global__ void mark_kernel(const int* __restrict__ roots,
                            const int* __restrict__ cnt0, const int* __restrict__ srcs0,
                            const int* __restrict__ cnt1, const int* __restrict__ srcs1,
                            char* mark0, char* mark1, int R) {
    int idx = blockIdx.x * blockDim.x + threadIdx.x;
    if (idx >= R * 65) return;
    int r = idx / 65;
    int s = idx % 65;
    const int* cnt; const int* srcs; char* mark;
    if (blockIdx.y) { cnt = cnt1; srcs = srcs1; mark = mark1; }
    else            { cnt = cnt0; srcs = srcs0; mark = mark0; }
    int node = __ldg(&roots[r]);
    if (s == 64) { mark[node] = 1; return; }
    int c = min(__ldg(&cnt[node]), SLOTS);
    if (s < c) mark[__ldg(&srcs[(size_t)node * SLOTS + s])] = 1;
}

__global__ void compact_kernel(const char* __restrict__ mark0, const char* __restrict__ mark1,
                               int* __restrict__ list0, int* __restrict__ list1,
                               int* __restrict__ inv0, int* __restrict__ inv1,
                               int* listcnt, int N) {
    int i = blockIdx.x * blockDim.x + threadIdx.x;
    if (i >= N) return;
    const char* mark; int* list; int* inv; int b = blockIdx.y;
    if (b) { mark = mark1; list = list1; inv = inv1; }
    else   { mark = mark0; list = list0; inv = inv0; }
    if (mark[i]) {
        int p = atomicAdd(&listcnt[b], 1);
        list[p] = i;
        inv[i] = p;
    }
}

// ---------------- x-space aggregation over S ----------------
// gx[idx] = dinv[node]*(sum dinv[s]*xh[s] + dinv[node]*xh[node])  (256-dim fp16)

__global__ __launch_bounds__(256)
void aggx_kernel(const uint32_t* __restrict__ xh, uint32_t* __restrict__ gx,
                 const int* __restrict__ cnt, const int* __restrict__ srcs,
                 const float* __restrict__ dinv,
                 const int* __restrict__ list, const int* __restrict__ listcnt) {
    int idx = (blockIdx.x * 256 + threadIdx.x) >> 5;
    if (idx >= __ldg(listcnt)) return;
    int node = __ldg(&list[idx]);
    int lane = threadIdx.x & 31;

    const uint4* X4 = (const uint4*)xh;       // row = 32 uint4 (256 halves)
    const float dd = __ldg(&dinv[node]);

    float acc[8];
    {
        uint4 v = __ldg(&X4[(size_t)node * 32 + lane]);
        float2 f0 = __half22float2(u32_h2(v.x));
        float2 f1 = __half22float2(u32_h2(v.y));
        float2 f2 = __half22float2(u32_h2(v.z));
        float2 f3 = __half22float2(u32_h2(v.w));
        acc[0] = dd * f0.x; acc[1] = dd * f0.y;
        acc[2] = dd * f1.x; acc[3] = dd * f1.y;
        acc[4] = dd * f2.x; acc[5] = dd * f2.y;
        acc[6] = dd * f3.x; acc[7] = dd * f3.y;
    }

    int c = min(__ldg(&cnt[node]), SLOTS);
    const int* sp = &srcs[(size_t)node * SLOTS];

    int i = 0;
    for (; i + 2 <= c; i += 2) {
        int s0 = __ldg(&sp[i]);
        int s1 = __ldg(&sp[i + 1]);
        float n0 = __ldg(&dinv[s0]);
        float n1 = __ldg(&dinv[s1]);
        uint4 v0 = __ldg(&X4[(size_t)s0 * 32 + lane]);
        uint4 v1 = __ldg(&X4[(size_t)s1 * 32 + lane]);
        float2 a0 = __half22float2(u32_h2(v0.x)), a1 = __half22float2(u32_h2(v0.y));
        float2 a2 = __half22float2(u32_h2(v0.z)), a3 = __half22float2(u32_h2(v0.w));
        acc[0] = fmaf(n0, a0.x, acc[0]); acc[1] = fmaf(n0, a0.y, acc[1]);
        acc[2] = fmaf(n0, a1.x, acc[2]); acc[3] = fmaf(n0, a1.y, acc[3]);
        acc[4] = fmaf(n0, a2.x, acc[4]); acc[5] = fmaf(n0, a2.y, acc[5]);
        acc[6] = fmaf(n0, a3.x, acc[6]); acc[7] = fmaf(n0, a3.y, acc[7]);
        float2 b0 = __half22float2(u32_h2(v1.x)), b1 = __half22float2(u32_h2(v1.y));
        float2 b2 = __half22float2(u32_h2(v1.z)), b3 = __half22float2(u32_h2(v1.w));
        acc[0] = fmaf(n1, b0.x, acc[0]); acc[1] = fmaf(n1, b0.y, acc[1]);
        acc[2] = fmaf(n1, b1.x, acc[2]); acc[3] = fmaf(n1, b1.y, acc[3]);
        acc[4] = fmaf(n1, b2.x, acc[4]); acc[5] = fmaf(n1, b2.y, acc[5]);
        acc[6] = fmaf(n1, b3.x, acc[6]); acc[7] = fmaf(n1, b3.y, acc[7]);
    }
    for (; i < c; i++) {
        int s = __ldg(&sp[i]);
        float n = __ldg(&dinv[s]);
        uint4 v = __ldg(&X4[(size_t)s * 32 + lane]);
        float2 a0 = __half22float2(u32_h2(v.x)), a1 = __half22float2(u32_h2(v.y));
        float2 a2 = __half22float2(u32_h2(v.z)), a3 = __half22float2(u32_h2(v.w));
        acc[0] = fmaf(n, a0.x, acc[0]); acc[1] = fmaf(n, a0.y, acc[1]);
        acc[2] = fmaf(n, a1.x, acc[2]); acc[3] = fmaf(n, a1.y, acc[3]);
        acc[4] = fmaf(n, a2.x, acc[4]); acc[5] = fmaf(n, a2.y, acc[5]);
        acc[6] = fmaf(n, a3.x, acc[6]); acc[7] = fmaf(n, a3.y, acc[7]);
    }

    uint4 o;
    o.x = h2_u32(__floats2half2_rn(dd * acc[0], dd * acc[1]));
    o.y = h2_u32(__floats2half2_rn(dd * acc[2], dd * acc[3]));
    o.z = h2_u32(__floats2half2_rn(dd * acc[4], dd * acc[5]));
    o.w = h2_u32(__floats2half2_rn(dd * acc[6], dd * acc[7]));
    ((uint4*)gx)[(size_t)idx * 32 + lane] = o;
}

// ---------------- fp16 mma helpers ----------------

__device__ __forceinline__ void mma_f16(float* c, const uint32_t* a, const uint32_t* b) {
    asm volatile(
        "mma.sync.aligned.m16n8k16.row.col.f32.f16.f16.f32 "
        "{%0,%1,%2,%3}, {%4,%5,%6,%7}, {%8,%9}, {%0,%1,%2,%3};"
        : "+f"(c[0]), "+f"(c[1]), "+f"(c[2]), "+f"(c[3])
        : "r"(a[0]), "r"(a[1]), "r"(a[2]), "r"(a[3]),
          "r"(b[0]), "r"(b[1]));
}

__device__ __forceinline__ int sw_idx(int k, int m) {
    return k * 136 + (m ^ (((k >> 2) & 3) << 3));
}

// ---------------- gemm_S: B1s[idx] = dinv[list[idx]]*elu(gx[idx]@W + b) -----
// compact rows; dynamic M from listcnt; K=256 fp16.

__global__ __launch_bounds__(256, 2)
void gemm_S(const uint32_t* __restrict__ X, const uint32_t* __restrict__ W,
            uint32_t* __restrict__ Y, const float* __restrict__ dinv,
            const float* __restrict__ bias,
            const int* __restrict__ list, const int* __restrict__ listcnt) {
    constexpr int K2 = 128;            // u32 per row (256 halves)
    constexpr int NC = 8;              // 8 k-tiles of 16 pairs

    const int M = __ldg(listcnt);
    const int row0 = blockIdx.x * 128;
    if (row0 >= M) return;

    __shared__ uint32_t xs[2][16 * 136];
    __shared__ uint32_t ws[2][16 * 136];

    const int tid  = threadIdx.x;
    const int lane = tid & 31;
    const int wid  = tid >> 5;
    const int g    = lane >> 2;
    const int tig  = lane & 3;
    const int mbase = (wid & 1) * 64;
    const int nbase = (wid >> 1) * 32;

    const int xr  = tid >> 2;
    const int xkq = (tid & 3) * 4;
    const int wkr = tid >> 5;
    const int wcq = (tid & 31) * 4;

    float c[4][4][4];
#pragma unroll
    for (int mf = 0; mf < 4; mf++)
#pragma unroll
        for (int nf = 0; nf < 4; nf++)
#pragma unroll
            for (int q = 0; q < 4; q++) c[mf][nf][q] = 0.f;

    uint4 xv[2], wv[2];

    auto loadg = [&](int t) {
        const int p0 = t * 16;
#pragma unroll
        for (int l = 0; l < 2; l++) {
            int r = xr + l * 64;
            int grow = row0 + r;
            xv[l] = (grow < M) ? *(const uint4*)&X[(size_t)grow * K2 + p0 + xkq]
                               : make_uint4(0u, 0u, 0u, 0u);
            wv[l] = *(const uint4*)&W[(size_t)(p0 + wkr + l * 8) * 128 + wcq];
        }
    };
    auto store_s = [&](int buf) {
#pragma unroll
        for (int l = 0; l < 2; l++) {
            int r = xr + l * 64;
            xs[buf][sw_idx(xkq + 0, r)] = xv[l].x;
            xs[buf][sw_idx(xkq + 1, r)] = xv[l].y;
            xs[buf][sw_idx(xkq + 2, r)] = xv[l].z;
            xs[buf][sw_idx(xkq + 3, r)] = xv[l].w;
            *(uint4*)&ws[buf][sw_idx(wkr + l * 8, wcq)] = wv[l];
        }
    };
    auto compute = [&](int buf) {
#pragma unroll
        for (int ks = 0; ks < 2; ks++) {
            const int klo = ks * 8 + tig;
            const int khi = klo + 4;
            uint32_t a[4][4], b[4][2];
#pragma unroll
            for (int mf = 0; mf < 4; mf++) {
                int m0 = mbase + mf * 16 + g;
                a[mf][0] = xs[buf][sw_idx(klo, m0)];
                a[mf][1] = xs[buf][sw_idx(klo, m0 + 8)];
                a[mf][2] = xs[buf][sw_idx(khi, m0)];
                a[mf][3] = xs[buf][sw_idx(khi, m0 + 8)];
            }
#pragma unroll
            for (int nf = 0; nf < 4; nf++) {
                int n0 = nbase + nf * 8 + g;
                b[nf][0] = ws[buf][sw_idx(klo, n0)];
                b[nf][1] = ws[buf][sw_idx(khi, n0)];
            }
#pragma unroll
            for (int mf = 0; mf < 4; mf++)
#pragma unroll
                for (int nf = 0; nf < 4; nf++)
                    mma_f16(c[mf][nf], a[mf], b[nf]);
        }
    };

    loadg(0);
    store_s(0);
    __syncthreads();

    for (int t = 0; t < NC; t++) {
        if (t + 1 < NC) loadg(t + 1);
        compute(t & 1);
        if (t + 1 < NC) {
            store_s((t + 1) & 1);
            __syncthreads();
        }
    }

#pragma unroll
    for (int mf = 0; mf < 4; mf++) {
        int r0 = row0 + mbase + mf * 16 + g;
        float dlo = 0.f, dhi = 0.f;
        if (r0 < M)     dlo = __ldg(&dinv[__ldg(&list[r0])]);
        if (r0 + 8 < M) dhi = __ldg(&dinv[__ldg(&list[r0 + 8])]);
#pragma unroll
        for (int nf = 0; nf < 4; nf++) {
            int ncol = nbase + nf * 8 + tig * 2;
            int np = ncol >> 1;
            float b0 = __ldg(&bias[ncol]);
            float b1 = __ldg(&bias[ncol + 1]);
            if (r0 < M)
                Y[(size_t)r0 * 64 + np] =
                    h2_u32(__floats2half2_rn(dlo * elu1(b0 + c[mf][nf][0]),
                                             dlo * elu1(b1 + c[mf][nf][1])));
            if (r0 + 8 < M)
                Y[(size_t)(r0 + 8) * 64 + np] =
                    h2_u32(__floats2half2_rn(dhi * elu1(b0 + c[mf][nf][2]),
                                             dhi * elu1(b1 + c[mf][nf][3])));
        }
    }
}

// ---------------- root layer-2 GEMM: elu(bias + g@W2) ----------------

__global__ __launch_bounds__(256, 2)
void gemm_root(const uint32_t* __restrict__ X, const uint32_t* __restrict__ W,
               uint32_t* __restrict__ Y, const float* __restrict__ bias, int M) {
    constexpr int K2 = 64;
    constexpr int NC = 4;

    __shared__ uint32_t xs[2][16 * 136];
    __shared__ uint32_t ws[2][16 * 136];

    const int tid  = threadIdx.x;
    const int lane = tid & 31;
    const int wid  = tid >> 5;
    const int g    = lane >> 2;
    const int tig  = lane & 3;
    const int mbase = (wid & 1) * 64;
    const int nbase = (wid >> 1) * 32;
    const int row0  = blockIdx.x * 128;

    const int xr  = tid >> 2;
    const int xkq = (tid & 3) * 4;
    const int wkr = tid >> 5;
    const int wcq = (tid & 31) * 4;

    float c[4][4][4];
#pragma unroll
    for (int mf = 0; mf < 4; mf++)
#pragma unroll
        for (int nf = 0; nf < 4; nf++)
#pragma unroll
            for (int q = 0; q < 4; q++) c[mf][nf][q] = 0.f;

    uint4 xv[2], wv[2];

    auto loadg = [&](int t) {
        const int p0 = t * 16;
#pragma unroll
        for (int l = 0; l < 2; l++) {
            int r = xr + l * 64;
            int grow = row0 + r;
            xv[l] = (grow < M) ? *(const uint4*)&X[(size_t)grow * K2 + p0 + xkq]
                               : make_uint4(0u, 0u, 0u, 0u);
            wv[l] = *(const uint4*)&W[(size_t)(p0 + wkr + l * 8) * 128 + wcq];
        }
    };
    auto store_s = [&](int buf) {
#pragma unroll
        for (int l = 0; l < 2; l++) {
            int r = xr + l * 64;
            xs[buf][sw_idx(xkq + 0, r)] = xv[l].x;
            xs[buf][sw_idx(xkq + 1, r)] = xv[l].y;
            xs[buf][sw_idx(xkq + 2, r)] = xv[l].z;
            xs[buf][sw_idx(xkq + 3, r)] = xv[l].w;
            *(uint4*)&ws[buf][sw_idx(wkr + l * 8, wcq)] = wv[l];
        }
    };
    auto compute = [&](int buf) {
#pragma unroll
        for (int ks = 0; ks < 2; ks++) {
            const int klo = ks * 8 + tig;
            const int khi = klo + 4;
            uint32_t a[4][4], b[4][2];
#pragma unroll
            for (int mf = 0; mf < 4; mf++) {
                int m0 = mbase + mf * 16 + g;
                a[mf][0] = xs[buf][sw_idx(klo, m0)];
                a[mf][1] = xs[buf][sw_idx(klo, m0 + 8)];
                a[mf][2] = xs[buf][sw_idx(khi, m0)];
                a[mf][3] = xs[buf][sw_idx(khi, m0 + 8)];
            }
#pragma unroll
            for (int nf = 0; nf < 4; nf++) {
                int n0 = nbase + nf * 8 + g;
                b[nf][0] = ws[buf][sw_idx(klo, n0)];
                b[nf][1] = ws[buf][sw_idx(khi, n0)];
            }
#pragma unroll
            for (int mf = 0; mf < 4; mf++)
#pragma unroll
                for (int nf = 0; nf < 4; nf++)
                    mma_f16(c[mf][nf], a[mf], b[nf]);
        }
    };

    loadg(0);
    store_s(0);
    __syncthreads();

    for (int t = 0; t < NC; t++) {
        if (t + 1 < NC) loadg(t + 1);
        compute(t & 1);
        if (t + 1 < NC) {
            store_s((t + 1) & 1);
            __syncthreads();
        }
    }

#pragma unroll
    for (int mf = 0; mf < 4; mf++) {
        int r0 = row0 + mbase + mf * 16 + g;
#pragma unroll
        for (int nf = 0; nf < 4; nf++) {
            int ncol = nbase + nf * 8 + tig * 2;
            int np = ncol >> 1;
            float b0 = __ldg(&bias[ncol]);
            float b1 = __ldg(&bias[ncol + 1]);
            if (r0 < M)
                Y[(size_t)r0 * 64 + np] =
                    h2_u32(__floats2half2_rn(elu1(b0 + c[mf][nf][0]),
                                             elu1(b1 + c[mf][nf][1])));
            if (r0 + 8 < M)
                Y[(size_t)(r0 + 8) * 64 + np] =
                    h2_u32(__floats2half2_rn(elu1(b0 + c[mf][nf][2]),
                                             elu1(b1 + c[mf][nf][3])));
        }
    }
}

// ---------------- layer-2 gather at roots (compact B1s via inv) -------------

__global__ __launch_bounds__(256)
void gather2_kernel(const uint32_t* __restrict__ B,
                    const int* __restrict__ roots,
                    const int* __restrict__ cnt, const int* __restrict__ srcs,
                    const float* __restrict__ dinv, const int* __restrict__ inv,
                    uint32_t* __restrict__ gbuf, int R) {
    int r = blockIdx.x * 8 + (threadIdx.x >> 5);
    if (r >= R) return;
    int lane = threadIdx.x & 31;
    int node = __ldg(&roots[r]);

    const uint2* B2 = (const uint2*)B;
    float4 acc = h4_to_f4(__ldg(&B2[(size_t)__ldg(&inv[node]) * 32 + lane]));

    int c = min(__ldg(&cnt[node]), SLOTS);
    const int* sp = &srcs[(size_t)node * SLOTS];
    for (int i = 0; i < c; i++) {
        int s = __ldg(&sp[i]);
        float4 v = h4_to_f4(__ldg(&B2[(size_t)__ldg(&inv[s]) * 32 + lane]));
        acc.x += v.x; acc.y += v.y; acc.z += v.z; acc.w += v.w;
    }

    float dd = __ldg(&dinv[node]);
    uint2 o;
    o.x = h2_u32(__floats2half2_rn(dd * acc.x, dd * acc.y));
    o.y = h2_u32(__floats2half2_rn(dd * acc.z, dd * acc.w));
    ((uint2*)gbuf)[(size_t)r * 32 + lane] = o;
}

// ---------------- fused head ----------------

__global__ __launch_bounds__(256)
void head_kernel(const uint32_t* __restrict__ Rtd, const uint32_t* __restrict__ Rbu,
                 const float* __restrict__ fcw, const float* __restrict__ fcb,
                 float* __restrict__ out, int R) {
    int r = blockIdx.x * 8 + (threadIdx.x >> 5);
    if (r >= R) return;
    int lane = threadIdx.x & 31;

    float4 ftd = h4_to_f4(((const uint2*)Rtd)[(size_t)r * 32 + lane]);
    float4 fbu = h4_to_f4(((const uint2*)Rbu)[(size_t)r * 32 + lane]);

    float s0 = 0.f, s1 = 0.f, s2 = 0.f, s3 = 0.f;
    const float* ft = &ftd.x;
    const float* fb = &fbu.x;
#pragma unroll
    for (int j = 0; j < 4; j++) {
        int k = lane * 4 + j;
        float4 wt = *(const float4*)&fcw[(size_t)k * 4];
        float4 wb = *(const float4*)&fcw[(size_t)(128 + k) * 4];
        s0 = fmaf(ft[j], wt.x, fmaf(fb[j], wb.x, s0));
        s1 = fmaf(ft[j], wt.y, fmaf(fb[j], wb.y, s1));
        s2 = fmaf(ft[j], wt.z, fmaf(fb[j], wb.z, s2));
        s3 = fmaf(ft[j], wt.w, fmaf(fb[j], wb.w, s3));
    }
#pragma unroll
    for (int off = 16; off; off >>= 1) {
        s0 += __shfl_xor_sync(0xffffffffu, s0, off);
        s1 += __shfl_xor_sync(0xffffffffu, s1, off);
        s2 += __shfl_xor_sync(0xffffffffu, s2, off);
        s3 += __shfl_xor_sync(0xffffffffu, s3, off);
    }
    if (lane == 0) {
        s0 += fcb[0]; s1 += fcb[1]; s2 += fcb[2]; s3 += fcb[3];
        float m = fmaxf(fmaxf(s0, s1), fmaxf(s2, s3));
        float s = expf(s0 - m) + expf(s1 - m) + expf(s2 - m) + expf(s3 - m);
        float lse = m + logf(s);
        float4 o = make_float4(s0 - lse, s1 - lse, s2 - lse, s3 - lse);
        *(float4*)&out[(size_t)r * 4] = o;
    }
}

// ---------------------------------------------------------------------------

extern "C" void kernel_launch(void* const* d_in, const int* in_sizes, int n_in,
                              void* d_out, int out_size) {
    const float* x       = (const float*)d_in[0];
    const int*   ei_td   = (const int*)d_in[1];
    const int*   ei_bu   = (const int*)d_in[2];
    const int*   rootidx = (const int*)d_in[3];
    const float* w1 = (const float*)d_in[4];
    const float* b1 = (const float*)d_in[5];
    const float* w2 = (const float*)d_in[6];
    const float* b2 = (const float*)d_in[7];
    const float* w3 = (const float*)d_in[8];
    const float* b3 = (const float*)d_in[9];
    const float* w4 = (const float*)d_in[10];
    const float* b4 = (const float*)d_in[11];
    const float* fcw = (const float*)d_in[12];
    const float* fcb = (const float*)d_in[13];
    float* out = (float*)d_out;

    const int N = in_sizes[0] / 256;
    const int E = in_sizes[1] / 2;
    const int R = in_sizes[3];

    const int* src_td = ei_td;
    const int* dst_td = ei_td + E;
    const int* src_bu = ei_bu;
    const int* dst_bu = ei_bu + E;

    uint32_t *xh, *gx_td, *gx_bu, *B_td, *B_bu, *wh, *g_td, *g_bu, *r_td, *r_bu;
    float *dinv_td, *dinv_bu;
    int *cur_td, *cur_bu, *srcs_td, *srcs_bu;
    int *list_td, *list_bu, *inv_td, *inv_bu, *listcnt;
    char *mark_td, *mark_bu;
    cudaGetSymbolAddress((void**)&xh, g_xh);
    cudaGetSymbolAddress((void**)&gx_td, g_gx_td);
    cudaGetSymbolAddress((void**)&gx_bu, g_gx_bu);
    cudaGetSymbolAddress((void**)&B_td, g_B_td);
    cudaGetSymbolAddress((void**)&B_bu, g_B_bu);
    cudaGetSymbolAddress((void**)&wh, g_wh);
    cudaGetSymbolAddress((void**)&cur_td, g_cur_td);
    cudaGetSymbolAddress((void**)&cur_bu, g_cur_bu);
    cudaGetSymbolAddress((void**)&dinv_td, g_dinv_td);
    cudaGetSymbolAddress((void**)&dinv_bu, g_dinv_bu);
    cudaGetSymbolAddress((void**)&srcs_td, g_srcs_td);
    cudaGetSymbolAddress((void**)&srcs_bu, g_srcs_bu);
    cudaGetSymbolAddress((void**)&mark_td, g_mark_td);
    cudaGetSymbolAddress((void**)&mark_bu, g_mark_bu);
    cudaGetSymbolAddress((void**)&list_td, g_list_td);
    cudaGetSymbolAddress((void**)&list_bu, g_list_bu);
    cudaGetSymbolAddress((void**)&inv_td, g_inv_td);
    cudaGetSymbolAddress((void**)&inv_bu, g_inv_bu);
    cudaGetSymbolAddress((void**)&listcnt, g_listcnt);
    cudaGetSymbolAddress((void**)&g_td, g_g_td);
    cudaGetSymbolAddress((void**)&g_bu, g_g_bu);
    cudaGetSymbolAddress((void**)&r_td, g_r_td);
    cudaGetSymbolAddress((void**)&r_bu, g_r_bu);

    const uint32_t* w1h = wh;                 // K=256 -> 128 pair rows
    const uint32_t* w2h = wh + 128 * 128;
    const uint32_t* w3h = wh + 192 * 128;
    const uint32_t* w4h = wh + 320 * 128;

    static cudaStream_t sB = nullptr, sC = nullptr;
    static cudaEvent_t evFork, evXh, evPrep, evWh, evBuDone;
    if (!sB) {
        cudaStreamCreateWithFlags(&sB, cudaStreamNonBlocking);
        cudaStreamCreateWithFlags(&sC, cudaStreamNonBlocking);
        cudaEventCreateWithFlags(&evFork,  cudaEventDisableTiming);
        cudaEventCreateWithFlags(&evXh,    cudaEventDisableTiming);
        cudaEventCreateWithFlags(&evPrep,  cudaEventDisableTiming);
        cudaEventCreateWithFlags(&evWh,    cudaEventDisableTiming);
        cudaEventCreateWithFlags(&evBuDone,cudaEventDisableTiming);
    }
    cudaStream_t sA = 0;

    const int agg_blocks = ceil_div(N, 8);      // early-exit on listcnt
    const int gemmS_blocks = ceil_div(N, 128);  // early-exit on listcnt
    const int root_gemm_blocks = ceil_div(R, 128);

    cudaEventRecord(evFork, sA);
    cudaStreamWaitEvent(sB, evFork, 0);
    cudaStreamWaitEvent(sC, evFork, 0);

    // sA: convert x -> fp16 (~16us)
    convert_x_kernel<<<ceil_div(N * 64, 256), 256, 0, sA>>>(x, xh, N * 64);
    cudaEventRecord(evXh, sA);

    // sB: prep chain: zero -> fill -> dinv -> mark -> compact (~45us)
    zero_kernel<<<ceil_div(N, 256), 256, 0, sB>>>(cur_td, cur_bu,
                                                  mark_td, mark_bu, listcnt, N);
    fill_kernel<<<dim3(ceil_div(E, 256), 2), 256, 0, sB>>>(
        src_td, dst_td, src_bu, dst_bu, cur_td, cur_bu, srcs_td, srcs_bu, E);
    dinv_kernel<<<ceil_div(N, 256), 256, 0, sB>>>(cur_td, cur_bu, dinv_td, dinv_bu, N);
    mark_kernel<<<dim3(ceil_div(R * 65, 256), 2), 256, 0, sB>>>(
        rootidx, cur_td, srcs_td, cur_bu, srcs_bu, mark_td, mark_bu, R);
    compact_kernel<<<dim3(ceil_div(N, 256), 2), 256, 0, sB>>>(
        mark_td, mark_bu, list_td, list_bu, inv_td, inv_bu, listcnt, N);
    cudaEventRecord(evPrep, sB);

    // sC: pack weights
    pack_w_kernel<<<192, 256, 0, sC>>>(w1, w2, w3, w4, wh);
    cudaEventRecord(evWh, sC);

    // --- td branch on sA ---
    cudaStreamWaitEvent(sA, evPrep, 0);
    aggx_kernel<<<agg_blocks, 256, 0, sA>>>(xh, gx_td, cur_td, srcs_td, dinv_td,
                                            list_td, &listcnt[0]);
    cudaStreamWaitEvent(sA, evWh, 0);
    gemm_S<<<gemmS_blocks, 256, 0, sA>>>(gx_td, w1h, B_td, dinv_td, b1,
                                         list_td, &listcnt[0]);
    gather2_kernel<<<ceil_div(R, 8), 256, 0, sA>>>(B_td, rootidx, cur_td, srcs_td,
                                                   dinv_td, inv_td, g_td, R);
    gemm_root<<<root_gemm_blocks, 256, 0, sA>>>(g_td, w2h, r_td, b2, R);

    // --- bu branch on sB ---
    cudaStreamWaitEvent(sB, evXh, 0);
    aggx_kernel<<<agg_blocks, 256, 0, sB>>>(xh, gx_bu, cur_bu, srcs_bu, dinv_bu,
                                            list_bu, &listcnt[1]);
    cudaStreamWaitEvent(sB, evWh, 0);
    gemm_S<<<gemmS_blocks, 256, 0, sB>>>(gx_bu, w3h, B_bu, dinv_bu, b3,
                                         list_bu, &listcnt[1]);
    gather2_kernel<<<ceil_div(R, 8), 256, 0, sB>>>(B_bu, rootidx, cur_bu, srcs_bu,
                                                   dinv_bu, inv_bu, g_bu, R);
    gemm_root<<<root_gemm_blocks, 256, 0, sB>>>(g_bu, w4h, r_bu, b4, R);
    cudaEventRecord(evBuDone, sB);

    // join + head
    cudaStreamWaitEvent(sA, evBuDone, 0);
    head_kernel<<<ceil_div(R, 8), 256, 0, sA>>>(r_td, r_bu, fcw, fcb, out, R);
}

// round 13
// speedup vs baseline: 1.0009x; 1.0009x over previous
#include <cuda_runtime.h>
#include <cuda_fp16.h>
#include <math.h>
#include <stdint.h>

// ---------------------------------------------------------------------------
// GCN_27797028339919 — round 13
//  * R12 math (aggregate-then-multiply on S = roots ∪ in-neigh(roots), root-
//    only layer 2) with a MINIMAL graph: 11 kernels, 2 events, 2 streams.
//  * branch-dual kernels via grid.y; dinv+compact fused.
// ---------------------------------------------------------------------------

#define MAX_N 100000
#define MAX_R 2048
#define SLOTS 64

__device__ uint32_t g_xh[(size_t)MAX_N * 128];
__device__ uint32_t g_gx_td[(size_t)MAX_N * 128];
__device__ uint32_t g_gx_bu[(size_t)MAX_N * 128];
__device__ uint32_t g_B_td[(size_t)MAX_N * 64];
__device__ uint32_t g_B_bu[(size_t)MAX_N * 64];
__device__ uint32_t g_wh[(size_t)384 * 128];
__device__ int   g_cur_td[MAX_N];
__device__ int   g_cur_bu[MAX_N];
__device__ float g_dinv_td[MAX_N];
__device__ float g_dinv_bu[MAX_N];
__device__ int   g_srcs_td[(size_t)MAX_N * SLOTS];
__device__ int   g_srcs_bu[(size_t)MAX_N * SLOTS];
__device__ char  g_mark_td[MAX_N];
__device__ char  g_mark_bu[MAX_N];
__device__ int   g_list_td[MAX_N];
__device__ int   g_list_bu[MAX_N];
__device__ int   g_inv_td[MAX_N];
__device__ int   g_inv_bu[MAX_N];
__device__ int   g_listcnt[2];
__device__ uint32_t g_g_td[(size_t)MAX_R * 64];
__device__ uint32_t g_g_bu[(size_t)MAX_R * 64];
__device__ uint32_t g_r_td[(size_t)MAX_R * 64];
__device__ uint32_t g_r_bu[(size_t)MAX_R * 64];

static inline int ceil_div(int a, int b) { return (a + b - 1) / b; }

__device__ __forceinline__ uint32_t h2_u32(__half2 h) {
    return *reinterpret_cast<uint32_t*>(&h);
}
__device__ __forceinline__ __half2 u32_h2(uint32_t u) {
    return *reinterpret_cast<__half2*>(&u);
}
__device__ __forceinline__ float4 h4_to_f4(uint2 v) {
    float2 lo = __half22float2(u32_h2(v.x));
    float2 hi = __half22float2(u32_h2(v.y));
    return make_float4(lo.x, lo.y, hi.x, hi.y);
}
__device__ __forceinline__ float elu1(float x) {
    return x > 0.f ? x : expm1f(x);
}

// ---------------- prep kernels ----------------

__global__ void convert_x_kernel(const float* __restrict__ x,
                                 uint32_t* __restrict__ xh, int n4) {
    int i = blockIdx.x * blockDim.x + threadIdx.x;
    if (i >= n4) return;
    float4 v = *(const float4*)&x[(size_t)i * 4];
    uint2 o;
    o.x = h2_u32(__floats2half2_rn(v.x, v.y));
    o.y = h2_u32(__floats2half2_rn(v.z, v.w));
    *(uint2*)&xh[(size_t)i * 2] = o;
}

__global__ void pack_w_kernel(const float* __restrict__ w1, const float* __restrict__ w2,
                              const float* __restrict__ w3, const float* __restrict__ w4,
                              uint32_t* __restrict__ wh) {
    int i = blockIdx.x * blockDim.x + threadIdx.x;
    if (i >= 384 * 128) return;
    int prow = i >> 7;
    int n = i & 127;
    const float* w; int p;
    if (prow < 128)      { w = w1; p = prow; }
    else if (prow < 192) { w = w2; p = prow - 128; }
    else if (prow < 320) { w = w3; p = prow - 192; }
    else                 { w = w4; p = prow - 320; }
    float a = w[(size_t)(2 * p) * 128 + n];
    float b = w[(size_t)(2 * p + 1) * 128 + n];
    wh[i] = h2_u32(__floats2half2_rn(a, b));
}

__global__ void zero_kernel(int* ua, int* ub, char* ma, char* mb, int* lc, int n) {
    int i = blockIdx.x * blockDim.x + threadIdx.x;
    if (i < n) { ua[i] = 0; ub[i] = 0; ma[i] = 0; mb[i] = 0; }
    if (i < 2) lc[i] = 0;
}

__global__ void fill_kernel(const int* __restrict__ src0, const int* __restrict__ dst0,
                            const int* __restrict__ src1, const int* __restrict__ dst1,
                            int* cur0, int* cur1,
                            int* __restrict__ srcs0, int* __restrict__ srcs1, int E) {
    int e = blockIdx.x * blockDim.x + threadIdx.x;
    if (e >= E) return;
    const int* src; const int* dst; int* cur; int* srcs;
    if (blockIdx.y) { src = src1; dst = dst1; cur = cur1; srcs = srcs1; }
    else            { src = src0; dst = dst0; cur = cur0; srcs = srcs0; }
    int d = __ldg(&dst[e]);
    int p = atomicAdd(&cur[d], 1);
    if (p < SLOTS) srcs[(size_t)d * SLOTS + p] = __ldg(&src[e]);
}

__global__ void mark_kernel(const int* __restrict__ roots,
                            const int* __restrict__ cnt0, const int* __restrict__ srcs0,
                            const int* __restrict__ cnt1, const int* __restrict__ srcs1,
                            char* mark0, char* mark1, int R) {
    int idx = blockIdx.x * blockDim.x + threadIdx.x;
    if (idx >= R * 65) return;
    int r = idx / 65;
    int s = idx % 65;
    const int* cnt; const int* srcs; char* mark;
    if (blockIdx.y) { cnt = cnt1; srcs = srcs1; mark = mark1; }
    else            { cnt = cnt0; srcs = srcs0; mark = mark0; }
    int node = __ldg(&roots[r]);
    if (s == 64) { mark[node] = 1; return; }
    int c = min(__ldg(&cnt[node]), SLOTS);
    if (s < c) mark[__ldg(&srcs[(size_t)node * SLOTS + s])] = 1;
}

// fused: dinv (both branches) + compact (both branches)
__global__ void dinvcompact_kernel(const int* __restrict__ cur0, const int* __restrict__ cur1,
                                   float* __restrict__ dinv0, float* __restrict__ dinv1,
                                   const char* __restrict__ mark0, const char* __restrict__ mark1,
                                   int* __restrict__ list0, int* __restrict__ list1,
                                   int* __restrict__ inv0, int* __restrict__ inv1,
                                   int* listcnt, int N) {
    int i = blockIdx.x * blockDim.x + threadIdx.x;
    if (i >= N) return;
    dinv0[i] = rsqrtf((float)__ldg(&cur0[i]) + 1.0f);
    dinv1[i] = rsqrtf((float)__ldg(&cur1[i]) + 1.0f);
    if (mark0[i]) { int p = atomicAdd(&listcnt[0], 1); list0[p] = i; inv0[i] = p; }
    if (mark1[i]) { int p = atomicAdd(&listcnt[1], 1); list1[p] = i; inv1[i] = p; }
}

// ---------------- x-space aggregation over S (dual) ----------------

__global__ __launch_bounds__(256)
void aggx_kernel(const uint32_t* __restrict__ xh,
                 uint32_t* __restrict__ gx0, uint32_t* __restrict__ gx1,
                 const int* __restrict__ cnt0, const int* __restrict__ cnt1,
                 const int* __restrict__ srcs0, const int* __restrict__ srcs1,
                 const float* __restrict__ dinv0, const float* __restrict__ dinv1,
                 const int* __restrict__ list0, const int* __restrict__ list1,
                 const int* __restrict__ listcnt) {
    uint32_t* gx; const int* cnt; const int* srcs; const float* dinv; const int* list;
    int lc;
    if (blockIdx.y) { gx = gx1; cnt = cnt1; srcs = srcs1; dinv = dinv1; list = list1; lc = __ldg(&listcnt[1]); }
    else            { gx = gx0; cnt = cnt0; srcs = srcs0; dinv = dinv0; list = list0; lc = __ldg(&listcnt[0]); }

    int idx = (blockIdx.x * 256 + threadIdx.x) >> 5;
    if (idx >= lc) return;
    int node = __ldg(&list[idx]);
    int lane = threadIdx.x & 31;

    const uint4* X4 = (const uint4*)xh;
    const float dd = __ldg(&dinv[node]);

    float acc[8];
    {
        uint4 v = __ldg(&X4[(size_t)node * 32 + lane]);
        float2 f0 = __half22float2(u32_h2(v.x));
        float2 f1 = __half22float2(u32_h2(v.y));
        float2 f2 = __half22float2(u32_h2(v.z));
        float2 f3 = __half22float2(u32_h2(v.w));
        acc[0] = dd * f0.x; acc[1] = dd * f0.y;
        acc[2] = dd * f1.x; acc[3] = dd * f1.y;
        acc[4] = dd * f2.x; acc[5] = dd * f2.y;
        acc[6] = dd * f3.x; acc[7] = dd * f3.y;
    }

    int c = min(__ldg(&cnt[node]), SLOTS);
    const int* sp = &srcs[(size_t)node * SLOTS];

    int i = 0;
    for (; i + 2 <= c; i += 2) {
        int s0 = __ldg(&sp[i]);
        int s1 = __ldg(&sp[i + 1]);
        float n0 = __ldg(&dinv[s0]);
        float n1 = __ldg(&dinv[s1]);
        uint4 v0 = __ldg(&X4[(size_t)s0 * 32 + lane]);
        uint4 v1 = __ldg(&X4[(size_t)s1 * 32 + lane]);
        float2 a0 = __half22float2(u32_h2(v0.x)), a1 = __half22float2(u32_h2(v0.y));
        float2 a2 = __half22float2(u32_h2(v0.z)), a3 = __half22float2(u32_h2(v0.w));
        acc[0] = fmaf(n0, a0.x, acc[0]); acc[1] = fmaf(n0, a0.y, acc[1]);
        acc[2] = fmaf(n0, a1.x, acc[2]); acc[3] = fmaf(n0, a1.y, acc[3]);
        acc[4] = fmaf(n0, a2.x, acc[4]); acc[5] = fmaf(n0, a2.y, acc[5]);
        acc[6] = fmaf(n0, a3.x, acc[6]); acc[7] = fmaf(n0, a3.y, acc[7]);
        float2 b0 = __half22float2(u32_h2(v1.x)), b1 = __half22float2(u32_h2(v1.y));
        float2 b2 = __half22float2(u32_h2(v1.z)), b3 = __half22float2(u32_h2(v1.w));
        acc[0] = fmaf(n1, b0.x, acc[0]); acc[1] = fmaf(n1, b0.y, acc[1]);
        acc[2] = fmaf(n1, b1.x, acc[2]); acc[3] = fmaf(n1, b1.y, acc[3]);
        acc[4] = fmaf(n1, b2.x, acc[4]); acc[5] = fmaf(n1, b2.y, acc[5]);
        acc[6] = fmaf(n1, b3.x, acc[6]); acc[7] = fmaf(n1, b3.y, acc[7]);
    }
    for (; i < c; i++) {
        int s = __ldg(&sp[i]);
        float n = __ldg(&dinv[s]);
        uint4 v = __ldg(&X4[(size_t)s * 32 + lane]);
        float2 a0 = __half22float2(u32_h2(v.x)), a1 = __half22float2(u32_h2(v.y));
        float2 a2 = __half22float2(u32_h2(v.z)), a3 = __half22float2(u32_h2(v.w));
        acc[0] = fmaf(n, a0.x, acc[0]); acc[1] = fmaf(n, a0.y, acc[1]);
        acc[2] = fmaf(n, a1.x, acc[2]); acc[3] = fmaf(n, a1.y, acc[3]);
        acc[4] = fmaf(n, a2.x, acc[4]); acc[5] = fmaf(n, a2.y, acc[5]);
        acc[6] = fmaf(n, a3.x, acc[6]); acc[7] = fmaf(n, a3.y, acc[7]);
    }

    uint4 o;
    o.x = h2_u32(__floats2half2_rn(dd * acc[0], dd * acc[1]));
    o.y = h2_u32(__floats2half2_rn(dd * acc[2], dd * acc[3]));
    o.z = h2_u32(__floats2half2_rn(dd * acc[4], dd * acc[5]));
    o.w = h2_u32(__floats2half2_rn(dd * acc[6], dd * acc[7]));
    ((uint4*)gx)[(size_t)idx * 32 + lane] = o;
}

// ---------------- fp16 mma helpers ----------------

__device__ __forceinline__ void mma_f16(float* c, const uint32_t* a, const uint32_t* b) {
    asm volatile(
        "mma.sync.aligned.m16n8k16.row.col.f32.f16.f16.f32 "
        "{%0,%1,%2,%3}, {%4,%5,%6,%7}, {%8,%9}, {%0,%1,%2,%3};"
        : "+f"(c[0]), "+f"(c[1]), "+f"(c[2]), "+f"(c[3])
        : "r"(a[0]), "r"(a[1]), "r"(a[2]), "r"(a[3]),
          "r"(b[0]), "r"(b[1]));
}

__device__ __forceinline__ int sw_idx(int k, int m) {
    return k * 136 + (m ^ (((k >> 2) & 3) << 3));
}

// ---------------- gemm_S dual: B1s[idx] = dinv[list[idx]]*elu(gx@W + b) -----

__global__ __launch_bounds__(256, 2)
void gemm_S(const uint32_t* __restrict__ X0, const uint32_t* __restrict__ X1,
            const uint32_t* __restrict__ W0, const uint32_t* __restrict__ W1,
            uint32_t* __restrict__ Y0, uint32_t* __restrict__ Y1,
            const float* __restrict__ dinv0, const float* __restrict__ dinv1,
            const float* __restrict__ bias0, const float* __restrict__ bias1,
            const int* __restrict__ list0, const int* __restrict__ list1,
            const int* __restrict__ listcnt) {
    const uint32_t* X; const uint32_t* W; uint32_t* Y;
    const float* dinv; const float* bias; const int* list; int M;
    if (blockIdx.y) { X = X1; W = W1; Y = Y1; dinv = dinv1; bias = bias1; list = list1; M = __ldg(&listcnt[1]); }
    else            { X = X0; W = W0; Y = Y0; dinv = dinv0; bias = bias0; list = list0; M = __ldg(&listcnt[0]); }

    constexpr int K2 = 128;
    constexpr int NC = 8;

    const int row0 = blockIdx.x * 128;
    if (row0 >= M) return;

    __shared__ uint32_t xs[2][16 * 136];
    __shared__ uint32_t ws[2][16 * 136];

    const int tid  = threadIdx.x;
    const int lane = tid & 31;
    const int wid  = tid >> 5;
    const int g    = lane >> 2;
    const int tig  = lane & 3;
    const int mbase = (wid & 1) * 64;
    const int nbase = (wid >> 1) * 32;

    const int xr  = tid >> 2;
    const int xkq = (tid & 3) * 4;
    const int wkr = tid >> 5;
    const int wcq = (tid & 31) * 4;

    float c[4][4][4];
#pragma unroll
    for (int mf = 0; mf < 4; mf++)
#pragma unroll
        for (int nf = 0; nf < 4; nf++)
#pragma unroll
            for (int q = 0; q < 4; q++) c[mf][nf][q] = 0.f;

    uint4 xv[2], wv[2];

    auto loadg = [&](int t) {
        const int p0 = t * 16;
#pragma unroll
        for (int l = 0; l < 2; l++) {
            int r = xr + l * 64;
            int grow = row0 + r;
            xv[l] = (grow < M) ? *(const uint4*)&X[(size_t)grow * K2 + p0 + xkq]
                               : make_uint4(0u, 0u, 0u, 0u);
            wv[l] = *(const uint4*)&W[(size_t)(p0 + wkr + l * 8) * 128 + wcq];
        }
    };
    auto store_s = [&](int buf) {
#pragma unroll
        for (int l = 0; l < 2; l++) {
            int r = xr + l * 64;
            xs[buf][sw_idx(xkq + 0, r)] = xv[l].x;
            xs[buf][sw_idx(xkq + 1, r)] = xv[l].y;
            xs[buf][sw_idx(xkq + 2, r)] = xv[l].z;
            xs[buf][sw_idx(xkq + 3, r)] = xv[l].w;
            *(uint4*)&ws[buf][sw_idx(wkr + l * 8, wcq)] = wv[l];
        }
    };
    auto compute = [&](int buf) {
#pragma unroll
        for (int ks = 0; ks < 2; ks++) {
            const int klo = ks * 8 + tig;
            const int khi = klo + 4;
            uint32_t a[4][4], b[4][2];
#pragma unroll
            for (int mf = 0; mf < 4; mf++) {
                int m0 = mbase + mf * 16 + g;
                a[mf][0] = xs[buf][sw_idx(klo, m0)];
                a[mf][1] = xs[buf][sw_idx(klo, m0 + 8)];
                a[mf][2] = xs[buf][sw_idx(khi, m0)];
                a[mf][3] = xs[buf][sw_idx(khi, m0 + 8)];
            }
#pragma unroll
            for (int nf = 0; nf < 4; nf++) {
                int n0 = nbase + nf * 8 + g;
                b[nf][0] = ws[buf][sw_idx(klo, n0)];
                b[nf][1] = ws[buf][sw_idx(khi, n0)];
            }
#pragma unroll
            for (int mf = 0; mf < 4; mf++)
#pragma unroll
                for (int nf = 0; nf < 4; nf++)
                    mma_f16(c[mf][nf], a[mf], b[nf]);
        }
    };

    loadg(0);
    store_s(0);
    __syncthreads();

    for (int t = 0; t < NC; t++) {
        if (t + 1 < NC) loadg(t + 1);
        compute(t & 1);
        if (t + 1 < NC) {
            store_s((t + 1) & 1);
            __syncthreads();
        }
    }

#pragma unroll
    for (int mf = 0; mf < 4; mf++) {
        int r0 = row0 + mbase + mf * 16 + g;
        float dlo = 0.f, dhi = 0.f;
        if (r0 < M)     dlo = __ldg(&dinv[__ldg(&list[r0])]);
        if (r0 + 8 < M) dhi = __ldg(&dinv[__ldg(&list[r0 + 8])]);
#pragma unroll
        for (int nf = 0; nf < 4; nf++) {
            int ncol = nbase + nf * 8 + tig * 2;
            int np = ncol >> 1;
            float b0 = __ldg(&bias[ncol]);
            float b1 = __ldg(&bias[ncol + 1]);
            if (r0 < M)
                Y[(size_t)r0 * 64 + np] =
                    h2_u32(__floats2half2_rn(dlo * elu1(b0 + c[mf][nf][0]),
                                             dlo * elu1(b1 + c[mf][nf][1])));
            if (r0 + 8 < M)
                Y[(size_t)(r0 + 8) * 64 + np] =
                    h2_u32(__floats2half2_rn(dhi * elu1(b0 + c[mf][nf][2]),
                                             dhi * elu1(b1 + c[mf][nf][3])));
        }
    }
}

// ---------------- root layer-2 GEMM dual: elu(bias + g@W) ----------------

__global__ __launch_bounds__(256, 2)
void gemm_root(const uint32_t* __restrict__ X0, const uint32_t* __restrict__ X1,
               const uint32_t* __restrict__ W0, const uint32_t* __restrict__ W1,
               uint32_t* __restrict__ Y0, uint32_t* __restrict__ Y1,
               const float* __restrict__ bias0, const float* __restrict__ bias1,
               int M) {
    const uint32_t* X; const uint32_t* W; uint32_t* Y; const float* bias;
    if (blockIdx.y) { X = X1; W = W1; Y = Y1; bias = bias1; }
    else            { X = X0; W = W0; Y = Y0; bias = bias0; }

    constexpr int K2 = 64;
    constexpr int NC = 4;

    __shared__ uint32_t xs[2][16 * 136];
    __shared__ uint32_t ws[2][16 * 136];

    const int tid  = threadIdx.x;
    const int lane = tid & 31;
    const int wid  = tid >> 5;
    const int g    = lane >> 2;
    const int tig  = lane & 3;
    const int mbase = (wid & 1) * 64;
    const int nbase = (wid >> 1) * 32;
    const int row0  = blockIdx.x * 128;

    const int xr  = tid >> 2;
    const int xkq = (tid & 3) * 4;
    const int wkr = tid >> 5;
    const int wcq = (tid & 31) * 4;

    float c[4][4][4];
#pragma unroll
    for (int mf = 0; mf < 4; mf++)
#pragma unroll
        for (int nf = 0; nf < 4; nf++)
#pragma unroll
            for (int q = 0; q < 4; q++) c[mf][nf][q] = 0.f;

    uint4 xv[2], wv[2];

    auto loadg = [&](int t) {
        const int p0 = t * 16;
#pragma unroll
        for (int l = 0; l < 2; l++) {
            int r = xr + l * 64;
            int grow = row0 + r;
            xv[l] = (grow < M) ? *(const uint4*)&X[(size_t)grow * K2 + p0 + xkq]
                               : make_uint4(0u, 0u, 0u, 0u);
            wv[l] = *(const uint4*)&W[(size_t)(p0 + wkr + l * 8) * 128 + wcq];
        }
    };
    auto store_s = [&](int buf) {
#pragma unroll
        for (int l = 0; l < 2; l++) {
            int r = xr + l * 64;
            xs[buf][sw_idx(xkq + 0, r)] = xv[l].x;
            xs[buf][sw_idx(xkq + 1, r)] = xv[l].y;
            xs[buf][sw_idx(xkq + 2, r)] = xv[l].z;
            xs[buf][sw_idx(xkq + 3, r)] = xv[l].w;
            *(uint4*)&ws[buf][sw_idx(wkr + l * 8, wcq)] = wv[l];
        }
    };
    auto compute = [&](int buf) {
#pragma unroll
        for (int ks = 0; ks < 2; ks++) {
            const int klo = ks * 8 + tig;
            const int khi = klo + 4;
            uint32_t a[4][4], b[4][2];
#pragma unroll
            for (int mf = 0; mf < 4; mf++) {
                int m0 = mbase + mf * 16 + g;
                a[mf][0] = xs[buf][sw_idx(klo, m0)];
                a[mf][1] = xs[buf][sw_idx(klo, m0 + 8)];
                a[mf][2] = xs[buf][sw_idx(khi, m0)];
                a[mf][3] = xs[buf][sw_idx(khi, m0 + 8)];
            }
#pragma unroll
            for (int nf = 0; nf < 4; nf++) {
                int n0 = nbase + nf * 8 + g;
                b[nf][0] = ws[buf][sw_idx(klo, n0)];
                b[nf][1] = ws[buf][sw_idx(khi, n0)];
            }
#pragma unroll
            for (int mf = 0; mf < 4; mf++)
#pragma unroll
                for (int nf = 0; nf < 4; nf++)
                    mma_f16(c[mf][nf], a[mf], b[nf]);
        }
    };

    loadg(0);
    store_s(0);
    __syncthreads();

    for (int t = 0; t < NC; t++) {
        if (t + 1 < NC) loadg(t + 1);
        compute(t & 1);
        if (t + 1 < NC) {
            store_s((t + 1) & 1);
            __syncthreads();
        }
    }

#pragma unroll
    for (int mf = 0; mf < 4; mf++) {
        int r0 = row0 + mbase + mf * 16 + g;
#pragma unroll
        for (int nf = 0; nf < 4; nf++) {
            int ncol = nbase + nf * 8 + tig * 2;
            int np = ncol >> 1;
            float b0 = __ldg(&bias[ncol]);
            float b1 = __ldg(&bias[ncol + 1]);
            if (r0 < M)
                Y[(size_t)r0 * 64 + np] =
                    h2_u32(__floats2half2_rn(elu1(b0 + c[mf][nf][0]),
                                             elu1(b1 + c[mf][nf][1])));
            if (r0 + 8 < M)
                Y[(size_t)(r0 + 8) * 64 + np] =
                    h2_u32(__floats2half2_rn(elu1(b0 + c[mf][nf][2]),
                                             elu1(b1 + c[mf][nf][3])));
        }
    }
}

// ---------------- layer-2 gather at roots (dual) ----------------

__global__ __launch_bounds__(256)
void gather2_kernel(const uint32_t* __restrict__ B0, const uint32_t* __restrict__ B1,
                    const int* __restrict__ roots,
                    const int* __restrict__ cnt0, const int* __restrict__ cnt1,
                    const int* __restrict__ srcs0, const int* __restrict__ srcs1,
                    const float* __restrict__ dinv0, const float* __restrict__ dinv1,
                    const int* __restrict__ inv0, const int* __restrict__ inv1,
                    uint32_t* __restrict__ gbuf0, uint32_t* __restrict__ gbuf1, int R) {
    const uint32_t* B; const int* cnt; const int* srcs; const float* dinv;
    const int* inv; uint32_t* gbuf;
    if (blockIdx.y) { B = B1; cnt = cnt1; srcs = srcs1; dinv = dinv1; inv = inv1; gbuf = gbuf1; }
    else            { B = B0; cnt = cnt0; srcs = srcs0; dinv = dinv0; inv = inv0; gbuf = gbuf0; }

    int r = blockIdx.x * 8 + (threadIdx.x >> 5);
    if (r >= R) return;
    int lane = threadIdx.x & 31;
    int node = __ldg(&roots[r]);

    const uint2* B2 = (const uint2*)B;
    float4 acc = h4_to_f4(__ldg(&B2[(size_t)__ldg(&inv[node]) * 32 + lane]));

    int c = min(__ldg(&cnt[node]), SLOTS);
    const int* sp = &srcs[(size_t)node * SLOTS];
    for (int i = 0; i < c; i++) {
        int s = __ldg(&sp[i]);
        float4 v = h4_to_f4(__ldg(&B2[(size_t)__ldg(&inv[s]) * 32 + lane]));
        acc.x += v.x; acc.y += v.y; acc.z += v.z; acc.w += v.w;
    }

    float dd = __ldg(&dinv[node]);
    uint2 o;
    o.x = h2_u32(__floats2half2_rn(dd * acc.x, dd * acc.y));
    o.y = h2_u32(__floats2half2_rn(dd * acc.z, dd * acc.w));
    ((uint2*)gbuf)[(size_t)r * 32 + lane] = o;
}

// ---------------- fused head ----------------

__global__ __launch_bounds__(256)
void head_kernel(const uint32_t* __restrict__ Rtd, const uint32_t* __restrict__ Rbu,
                 const float* __restrict__ fcw, const float* __restrict__ fcb,
                 float* __restrict__ out, int R) {
    int r = blockIdx.x * 8 + (threadIdx.x >> 5);
    if (r >= R) return;
    int lane = threadIdx.x & 31;

    float4 ftd = h4_to_f4(((const uint2*)Rtd)[(size_t)r * 32 + lane]);
    float4 fbu = h4_to_f4(((const uint2*)Rbu)[(size_t)r * 32 + lane]);

    float s0 = 0.f, s1 = 0.f, s2 = 0.f, s3 = 0.f;
    const float* ft = &ftd.x;
    const float* fb = &fbu.x;
#pragma unroll
    for (int j = 0; j < 4; j++) {
        int k = lane * 4 + j;
        float4 wt = *(const float4*)&fcw[(size_t)k * 4];
        float4 wb = *(const float4*)&fcw[(size_t)(128 + k) * 4];
        s0 = fmaf(ft[j], wt.x, fmaf(fb[j], wb.x, s0));
        s1 = fmaf(ft[j], wt.y, fmaf(fb[j], wb.y, s1));
        s2 = fmaf(ft[j], wt.z, fmaf(fb[j], wb.z, s2));
        s3 = fmaf(ft[j], wt.w, fmaf(fb[j], wb.w, s3));
    }
#pragma unroll
    for (int off = 16; off; off >>= 1) {
        s0 += __shfl_xor_sync(0xffffffffu, s0, off);
        s1 += __shfl_xor_sync(0xffffffffu, s1, off);
        s2 += __shfl_xor_sync(0xffffffffu, s2, off);
        s3 += __shfl_xor_sync(0xffffffffu, s3, off);
    }
    if (lane == 0) {
        s0 += fcb[0]; s1 += fcb[1]; s2 += fcb[2]; s3 += fcb[3];
        float m = fmaxf(fmaxf(s0, s1), fmaxf(s2, s3));
        float s = expf(s0 - m) + expf(s1 - m) + expf(s2 - m) + expf(s3 - m);
        float lse = m + logf(s);
        float4 o = make_float4(s0 - lse, s1 - lse, s2 - lse, s3 - lse);
        *(float4*)&out[(size_t)r * 4] = o;
    }
}

// ---------------------------------------------------------------------------

extern "C" void kernel_launch(void* const* d_in, const int* in_sizes, int n_in,
                              void* d_out, int out_size) {
    const float* x       = (const float*)d_in[0];
    const int*   ei_td   = (const int*)d_in[1];
    const int*   ei_bu   = (const int*)d_in[2];
    const int*   rootidx = (const int*)d_in[3];
    const float* w1 = (const float*)d_in[4];
    const float* b1 = (const float*)d_in[5];
    const float* w2 = (const float*)d_in[6];
    const float* b2 = (const float*)d_in[7];
    const float* w3 = (const float*)d_in[8];
    const float* b3 = (const float*)d_in[9];
    const float* w4 = (const float*)d_in[10];
    const float* b4 = (const float*)d_in[11];
    const float* fcw = (const float*)d_in[12];
    const float* fcb = (const float*)d_in[13];
    float* out = (float*)d_out;

    const int N = in_sizes[0] / 256;
    const int E = in_sizes[1] / 2;
    const int R = in_sizes[3];

    const int* src_td = ei_td;
    const int* dst_td = ei_td + E;
    const int* src_bu = ei_bu;
    const int* dst_bu = ei_bu + E;

    uint32_t *xh, *gx_td, *gx_bu, *B_td, *B_bu, *wh, *g_td, *g_bu, *r_td, *r_bu;
    float *dinv_td, *dinv_bu;
    int *cur_td, *cur_bu, *srcs_td, *srcs_bu;
    int *list_td, *list_bu, *inv_td, *inv_bu, *listcnt;
    char *mark_td, *mark_bu;
    cudaGetSymbolAddress((void**)&xh, g_xh);
    cudaGetSymbolAddress((void**)&gx_td, g_gx_td);
    cudaGetSymbolAddress((void**)&gx_bu, g_gx_bu);
    cudaGetSymbolAddress((void**)&B_td, g_B_td);
    cudaGetSymbolAddress((void**)&B_bu, g_B_bu);
    cudaGetSymbolAddress((void**)&wh, g_wh);
    cudaGetSymbolAddress((void**)&cur_td, g_cur_td);
    cudaGetSymbolAddress((void**)&cur_bu, g_cur_bu);
    cudaGetSymbolAddress((void**)&dinv_td, g_dinv_td);
    cudaGetSymbolAddress((void**)&dinv_bu, g_dinv_bu);
    cudaGetSymbolAddress((void**)&srcs_td, g_srcs_td);
    cudaGetSymbolAddress((void**)&srcs_bu, g_srcs_bu);
    cudaGetSymbolAddress((void**)&mark_td, g_mark_td);
    cudaGetSymbolAddress((void**)&mark_bu, g_mark_bu);
    cudaGetSymbolAddress((void**)&list_td, g_list_td);
    cudaGetSymbolAddress((void**)&list_bu, g_list_bu);
    cudaGetSymbolAddress((void**)&inv_td, g_inv_td);
    cudaGetSymbolAddress((void**)&inv_bu, g_inv_bu);
    cudaGetSymbolAddress((void**)&listcnt, g_listcnt);
    cudaGetSymbolAddress((void**)&g_td, g_g_td);
    cudaGetSymbolAddress((void**)&g_bu, g_g_bu);
    cudaGetSymbolAddress((void**)&r_td, g_r_td);
    cudaGetSymbolAddress((void**)&r_bu, g_r_bu);

    const uint32_t* w1h = wh;
    const uint32_t* w2h = wh + 128 * 128;
    const uint32_t* w3h = wh + 192 * 128;
    const uint32_t* w4h = wh + 320 * 128;

    static cudaStream_t sB = nullptr;
    static cudaEvent_t evFork, evPrep;
    if (!sB) {
        cudaStreamCreateWithFlags(&sB, cudaStreamNonBlocking);
        cudaEventCreateWithFlags(&evFork, cudaEventDisableTiming);
        cudaEventCreateWithFlags(&evPrep, cudaEventDisableTiming);
    }
    cudaStream_t sA = 0;

    const dim3 agg_grid(ceil_div(N, 8), 2);
    const dim3 gemmS_grid(ceil_div(N, 128), 2);
    const dim3 gather_grid(ceil_div(R, 8), 2);
    const dim3 root_grid(ceil_div(R, 128), 2);

    cudaEventRecord(evFork, sA);
    cudaStreamWaitEvent(sB, evFork, 0);

    // sB: prep chain (hidden under sA's convert+pack, then gates aggx)
    zero_kernel<<<ceil_div(N, 256), 256, 0, sB>>>(cur_td, cur_bu,
                                                  mark_td, mark_bu, listcnt, N);
    fill_kernel<<<dim3(ceil_div(E, 256), 2), 256, 0, sB>>>(
        src_td, dst_td, src_bu, dst_bu, cur_td, cur_bu, srcs_td, srcs_bu, E);
    mark_kernel<<<dim3(ceil_div(R * 65, 256), 2), 256, 0, sB>>>(
        rootidx, cur_td, srcs_td, cur_bu, srcs_bu, mark_td, mark_bu, R);
    dinvcompact_kernel<<<ceil_div(N, 256), 256, 0, sB>>>(
        cur_td, cur_bu, dinv_td, dinv_bu, mark_td, mark_bu,
        list_td, list_bu, inv_td, inv_bu, listcnt, N);
    cudaEventRecord(evPrep, sB);

    // sA: convert + pack (independent), then the whole compute tail
    convert_x_kernel<<<ceil_div(N * 64, 256), 256, 0, sA>>>(x, xh, N * 64);
    pack_w_kernel<<<192, 256, 0, sA>>>(w1, w2, w3, w4, wh);
    cudaStreamWaitEvent(sA, evPrep, 0);
    aggx_kernel<<<agg_grid, 256, 0, sA>>>(xh, gx_td, gx_bu, cur_td, cur_bu,
                                          srcs_td, srcs_bu, dinv_td, dinv_bu,
                                          list_td, list_bu, listcnt);
    gemm_S<<<gemmS_grid, 256, 0, sA>>>(gx_td, gx_bu, w1h, w3h, B_td, B_bu,
                                       dinv_td, dinv_bu, b1, b3,
                                       list_td, list_bu, listcnt);
    gather2_kernel<<<gather_grid, 256, 0, sA>>>(B_td, B_bu, rootidx,
                                                cur_td, cur_bu, srcs_td, srcs_bu,
                                                dinv_td, dinv_bu, inv_td, inv_bu,
                                                g_td, g_bu, R);
    gemm_root<<<root_grid, 256, 0, sA>>>(g_td, g_bu, w2h, w4h, r_td, r_bu,
                                         b2, b4, R);
    head_kernel<<<ceil_div(R, 8), 256, 0, sA>>>(r_td, r_bu, fcw, fcb, out, R);
}